// round 2
// baseline (speedup 1.0000x reference)
#include <cuda_runtime.h>
#include <cuda_bf16.h>
#include <math.h>

#define NMAX 200000
#define EPS 1e-15f

// Per-node accumulator: {denom, pad, msum.x, msum.y} — 16B aligned for red.v4
__device__ __align__(16) float4 g_accum[NMAX];

// v = log_{xi}(xj) on the Poincare disk (c = 1)
__device__ __forceinline__ float2 compute_v(float2 xi, float2 xj) {
    float ab = -(xi.x * xj.x + xi.y * xj.y);     // <-xi, xj>
    float aa = xi.x * xi.x + xi.y * xi.y;        // |xi|^2
    float bb = xj.x * xj.x + xj.y * xj.y;        // |xj|^2
    float f1 = 1.0f + 2.0f * ab + bb;            // coeff of (-xi)
    float f2 = 1.0f - aa;                        // coeff of xj
    float den = 1.0f + 2.0f * ab + aa * bb;
    float inv_den = 1.0f / fmaxf(den, EPS);
    float ux = (f1 * (-xi.x) + f2 * xj.x) * inv_den;
    float uy = (f1 * (-xi.y) + f2 * xj.y) * inv_den;
    float un = fmaxf(sqrtf(ux * ux + uy * uy), EPS);
    // (2 / lam_i) = (1 - aa);  s = (1-aa) * atanh(min(un,1-1e-5)) / un
    float t = fminf(un, 1.0f - 1e-5f);
    float s = f2 * atanhf(t) / un;
    return make_float2(s * ux, s * uy);
}

__device__ __forceinline__ float mlp_score(float2 v, const float* sW1,
                                           const float* sb1, const float* sW2) {
    float score = 0.0f;
#pragma unroll
    for (int k = 0; k < 16; k++) {
        float h = fmaf(v.x, sW1[k], fmaf(v.y, sW1[16 + k], sb1[k]));
        float g = 0.5f * h * (1.0f + erff(h * 0.70710678118654752f));
        score = fmaf(g, sW2[k], score);
    }
    return score;
}

__global__ void init_kernel(int n) {
    int i = blockIdx.x * blockDim.x + threadIdx.x;
    if (i < n) g_accum[i] = make_float4(0.0f, 0.0f, 0.0f, 0.0f);
}

__global__ void __launch_bounds__(256) edge_pass(
        const float2* __restrict__ x,
        const int* __restrict__ row,
        const int* __restrict__ col,
        const float* __restrict__ W1,
        const float* __restrict__ b1,
        const float* __restrict__ W2, int E) {
    __shared__ float sW1[32], sb1[16], sW2[16];
    int t = threadIdx.x;
    if (t < 32)      sW1[t] = W1[t];
    else if (t < 48) sb1[t - 32] = b1[t - 32];
    else if (t < 64) sW2[t - 48] = W2[t - 48];
    __syncthreads();

    int e = blockIdx.x * blockDim.x + t;
    if (e >= E) return;
    int r = __ldg(&row[e]);
    int c = __ldg(&col[e]);
    float2 v = compute_v(__ldg(&x[r]), __ldg(&x[c]));
    float score = mlp_score(v, sW1, sb1, sW2);
    // Unshifted softmax numerator: scores are bounded (|s| << 88), no overflow.
    float ex = expf(score);
    float vx = ex * v.x, vy = ex * v.y;
    asm volatile("red.global.v4.f32.add [%0], {%1, %2, %3, %4};"
                 :: "l"(&g_accum[r]), "f"(ex), "f"(0.0f), "f"(vx), "f"(vy)
                 : "memory");
}

__global__ void __launch_bounds__(256) node_pass(
        const float2* __restrict__ x,
        const int* __restrict__ depth,
        const float* __restrict__ eta_p,
        const float* __restrict__ depth_scale,
        const float* __restrict__ depth_theta,
        float* __restrict__ out, int n) {
    int i = blockIdx.x * blockDim.x + threadIdx.x;
    if (i >= n) return;
    float eta = __ldg(eta_p);
    float2 xv = __ldg(&x[i]);
    float4 acc = g_accum[i];
    float inv_d = 1.0f / fmaxf(acc.x, 1e-15f);
    float mx = acc.z * inv_d, my = acc.w * inv_d;

    int d = min(max(depth[i], 0), 511);
    float k = __ldg(&depth_scale[d]);
    float ang = __ldg(&depth_theta[d]);
    float sa, ca;
    __sincosf(ang, &sa, &ca);
    float rx = k * (ca * mx - sa * my);
    float ry = k * (sa * mx + ca * my);

    // exp_x(eta * m)
    float wx = eta * rx, wy = eta * ry;
    float wn = fmaxf(sqrtf(wx * wx + wy * wy), EPS);
    float aa = xv.x * xv.x + xv.y * xv.y;
    float lam = 2.0f / fmaxf(1.0f - aa, EPS);
    float th = tanhf(lam * wn * 0.5f);
    float sxv = th * wx / wn;
    float syv = th * wy / wn;

    // mobius_add(x, second, 1)
    float ab = xv.x * sxv + xv.y * syv;
    float bb = sxv * sxv + syv * syv;
    float fa = 1.0f + 2.0f * ab + bb;
    float fb = 1.0f - aa;
    float den = 1.0f + 2.0f * ab + aa * bb;
    float inv = 1.0f / fmaxf(den, EPS);
    out[2 * i]     = (fa * xv.x + fb * sxv) * inv;
    out[2 * i + 1] = (fa * xv.y + fb * syv) * inv;
}

extern "C" void kernel_launch(void* const* d_in, const int* in_sizes, int n_in,
                              void* d_out, int out_size) {
    const float* x           = (const float*)d_in[0];   // [N,2]
    const int*   edge_index  = (const int*)d_in[1];     // [2,E]
    const int*   depth       = (const int*)d_in[2];     // [N]
    const float* W1          = (const float*)d_in[3];   // [2,16]
    const float* b1          = (const float*)d_in[4];   // [16]
    const float* W2          = (const float*)d_in[5];   // [16,1]
    const float* eta         = (const float*)d_in[6];   // scalar
    const float* depth_scale = (const float*)d_in[7];   // [512,1]
    const float* depth_theta = (const float*)d_in[8];   // [512,1]
    float* out = (float*)d_out;

    int N = in_sizes[0] / 2;
    int E = in_sizes[1] / 2;
    const int* row = edge_index;
    const int* col = edge_index + E;
    const float2* x2 = (const float2*)x;

    int tb = 256;
    init_kernel<<<(N + tb - 1) / tb, tb>>>(N);
    edge_pass<<<(E + tb - 1) / tb, tb>>>(x2, row, col, W1, b1, W2, E);
    node_pass<<<(N + tb - 1) / tb, tb>>>(x2, depth, eta, depth_scale, depth_theta, out, N);
}